// round 1
// baseline (speedup 1.0000x reference)
#include <cuda_runtime.h>
#include <math_constants.h>

#define B_  32
#define N_  1024
#define F_  64
#define K_  16
#define P_  128
#define H_  256   // 2*P

// scratch: neighbor indices (B,N,K)
__device__ int g_idx[B_ * N_ * K_];

// ---------------------------------------------------------------------------
// Kernel 1: pairwise distances + top-(K+1) selection (drop self).
// One thread per query row; all 1024 points of the batch staged in SMEM.
// Matches reference: D = r - 2*dot + r^T + 1e-5, ties -> lower index first.
// ---------------------------------------------------------------------------
__global__ __launch_bounds__(256) void knn_kernel(const float* __restrict__ points)
{
    __shared__ float4 pts[N_];
    int b = blockIdx.x >> 2;
    int rowbase = (blockIdx.x & 3) << 8;
    const float* P = points + (size_t)b * N_ * 3;
    for (int i = threadIdx.x; i < N_; i += 256) {
        float x = P[i * 3 + 0], y = P[i * 3 + 1], z = P[i * 3 + 2];
        pts[i] = make_float4(x, y, z, x * x + y * y + z * z);
    }
    __syncthreads();

    int n = rowbase + threadIdx.x;
    float4 pn = pts[n];

    float dist[K_ + 1];
    int   nbr[K_ + 1];
#pragma unroll
    for (int j = 0; j <= K_; j++) { dist[j] = CUDART_INF_F; nbr[j] = 0; }
    float worst = CUDART_INF_F;

    for (int m = 0; m < N_; m++) {
        float4 pm = pts[m];
        float dot = pn.x * pm.x + pn.y * pm.y + pn.z * pm.z;
        float d = pn.w - 2.0f * dot + pm.w + 1e-5f;
        if (d < worst) {
            int j = K_;
            for (; j > 0; j--) {
                if (dist[j - 1] > d) { dist[j] = dist[j - 1]; nbr[j] = nbr[j - 1]; }
                else break;
            }
            dist[j] = d; nbr[j] = m;
            worst = dist[K_];
        }
    }

    int* o = g_idx + ((size_t)b * N_ + n) * K_;
#pragma unroll
    for (int k = 0; k < K_; k++) o[k] = nbr[k + 1];   // drop self (entry 0)
}

// ---------------------------------------------------------------------------
// Packed f32x2 helpers (sm_103a FFMA2 path — 2x fp32 FMA lanes per instr)
// ---------------------------------------------------------------------------
__device__ __forceinline__ unsigned long long pack2(float lo, float hi)
{
    unsigned long long r;
    asm("mov.b64 %0, {%1, %2};" : "=l"(r) : "f"(lo), "f"(hi));
    return r;
}
__device__ __forceinline__ void unpack2(unsigned long long v, float& lo, float& hi)
{
    asm("mov.b64 {%0, %1}, %2;" : "=f"(lo), "=f"(hi) : "l"(v));
}
__device__ __forceinline__ unsigned long long ffma2(unsigned long long a,
                                                    unsigned long long b,
                                                    unsigned long long c)
{
    unsigned long long d;
    asm("fma.rn.f32x2 %0, %1, %2, %3;" : "=l"(d) : "l"(a), "l"(b), "l"(c));
    return d;
}

__device__ __forceinline__ float gelu_exact(float x)
{
    return 0.5f * x * (1.0f + erff(x * 0.70710678118654752440f));
}

// ---------------------------------------------------------------------------
// Kernel 2: fused edge MLP + mean over K.
// One block per (b, n). 256 threads.
//   gather:  local[k][0:64] = feat[nbr]-feat[n], local[k][64:128] = feat[n]
//   phase 1: thread j computes H[k][j] = gelu(local[k]·W1[:,j] + b1[j]), k=0..15
//            (reduction over f packed into f32x2 lanes: even f in lo, odd in hi)
//   phase 2: thread (p, k-half) computes gelu(H[k]·W2[:,p] + b2[p]) and sums
//            over its 8 k; two halves combined -> mean/16
// ---------------------------------------------------------------------------
__global__ __launch_bounds__(256) void mlp_kernel(
    const float* __restrict__ features,
    const float* __restrict__ W1, const float* __restrict__ b1,
    const float* __restrict__ W2, const float* __restrict__ b2,
    float* __restrict__ out)
{
    __shared__ __align__(16) float local[K_][2 * F_];   // 8 KB
    __shared__ __align__(16) float Hs[K_][H_];          // 16 KB
    __shared__ float cen[F_];
    __shared__ int   nb[K_];
    __shared__ float partial[P_];

    int bn = blockIdx.x;
    int b = bn >> 10;
    int n = bn & 1023;
    const float* Fb = features + (size_t)b * N_ * F_;
    int t = threadIdx.x;

    if (t < F_) cen[t] = Fb[(size_t)n * F_ + t];
    if (t >= 128 && t < 128 + K_) nb[t - 128] = g_idx[(size_t)bn * K_ + (t - 128)];
    __syncthreads();

    for (int e = t; e < K_ * F_; e += 256) {
        int k = e >> 6, f = e & 63;
        float c = cen[f];
        float v = Fb[(size_t)nb[k] * F_ + f];
        local[k][f]      = v - c;
        local[k][F_ + f] = c;
    }
    __syncthreads();

    // ---------------- phase 1 ----------------
    {
        int j = t;                       // column of H, 0..255
        unsigned long long acc[K_];
        unsigned long long init = pack2(b1[j], 0.0f);
#pragma unroll
        for (int k = 0; k < K_; k++) acc[k] = init;

        for (int f = 0; f < 2 * F_; f += 4) {
            float w0 = W1[(f + 0) * H_ + j];
            float w1v = W1[(f + 1) * H_ + j];
            float w2v = W1[(f + 2) * H_ + j];
            float w3v = W1[(f + 3) * H_ + j];
            unsigned long long wp0 = pack2(w0, w1v);
            unsigned long long wp1 = pack2(w2v, w3v);
#pragma unroll
            for (int k = 0; k < K_; k++) {
                const unsigned long long* lp =
                    reinterpret_cast<const unsigned long long*>(&local[k][f]);
                acc[k] = ffma2(lp[0], wp0, acc[k]);
                acc[k] = ffma2(lp[1], wp1, acc[k]);
            }
        }
#pragma unroll
        for (int k = 0; k < K_; k++) {
            float lo, hi; unpack2(acc[k], lo, hi);
            Hs[k][j] = gelu_exact(lo + hi);
        }
    }
    __syncthreads();

    // ---------------- phase 2 ----------------
    {
        int p  = t & 127;
        int kh = t >> 7;                 // 0 -> k 0..7, 1 -> k 8..15
        unsigned long long acc[8];
        unsigned long long init = pack2(b2[p], 0.0f);
#pragma unroll
        for (int q = 0; q < 8; q++) acc[q] = init;

        for (int j = 0; j < H_; j += 4) {
            float w0 = W2[(j + 0) * P_ + p];
            float w1v = W2[(j + 1) * P_ + p];
            float w2v = W2[(j + 2) * P_ + p];
            float w3v = W2[(j + 3) * P_ + p];
            unsigned long long wp0 = pack2(w0, w1v);
            unsigned long long wp1 = pack2(w2v, w3v);
#pragma unroll
            for (int q = 0; q < 8; q++) {
                const unsigned long long* hp =
                    reinterpret_cast<const unsigned long long*>(&Hs[kh * 8 + q][j]);
                acc[q] = ffma2(hp[0], wp0, acc[q]);
                acc[q] = ffma2(hp[1], wp1, acc[q]);
            }
        }

        float s = 0.0f;
#pragma unroll
        for (int q = 0; q < 8; q++) {
            float lo, hi; unpack2(acc[q], lo, hi);
            s += gelu_exact(lo + hi);
        }
        if (kh) partial[p] = s;
        __syncthreads();
        if (!kh) out[(size_t)bn * P_ + p] = (s + partial[p]) * (1.0f / 16.0f);
    }
}

// ---------------------------------------------------------------------------
extern "C" void kernel_launch(void* const* d_in, const int* in_sizes, int n_in,
                              void* d_out, int out_size)
{
    const float* points   = (const float*)d_in[0];
    const float* features = (const float*)d_in[1];
    const float* W1       = (const float*)d_in[2];
    const float* b1       = (const float*)d_in[3];
    const float* W2       = (const float*)d_in[4];
    const float* b2       = (const float*)d_in[5];
    float* out = (float*)d_out;

    knn_kernel<<<B_ * 4, 256>>>(points);
    mlp_kernel<<<B_ * N_, 256>>>(features, W1, b1, W2, b2, out);
}

// round 4
// speedup vs baseline: 1.1162x; 1.1162x over previous
#include <cuda_runtime.h>
#include <math_constants.h>

#define B_   32
#define N_   1024
#define F_   64
#define K_   16
#define P_   128
#define H_   256     // 2*P
#define NPB  4       // points per block
#define M_   (NPB * K_)   // 64 GEMM rows per block
#define AST  66      // padded SMEM row stride (floats)
#define HST  66

typedef unsigned long long ull;

__device__ int g_idx[B_ * N_ * K_];

// ---------------------------------------------------------------------------
// Kernel 1: pairwise distances + top-(K+1) selection (drop self). Unchanged.
// ---------------------------------------------------------------------------
__global__ __launch_bounds__(256) void knn_kernel(const float* __restrict__ points)
{
    __shared__ float4 pts[N_];
    int b = blockIdx.x >> 2;
    int rowbase = (blockIdx.x & 3) << 8;
    const float* P = points + (size_t)b * N_ * 3;
    for (int i = threadIdx.x; i < N_; i += 256) {
        float x = P[i * 3 + 0], y = P[i * 3 + 1], z = P[i * 3 + 2];
        pts[i] = make_float4(x, y, z, x * x + y * y + z * z);
    }
    __syncthreads();

    int n = rowbase + threadIdx.x;
    float4 pn = pts[n];

    float dist[K_ + 1];
    int   nbr[K_ + 1];
#pragma unroll
    for (int j = 0; j <= K_; j++) { dist[j] = CUDART_INF_F; nbr[j] = 0; }
    float worst = CUDART_INF_F;

    for (int m = 0; m < N_; m++) {
        float4 pm = pts[m];
        float dot = pn.x * pm.x + pn.y * pm.y + pn.z * pm.z;
        float d = pn.w - 2.0f * dot + pm.w + 1e-5f;
        if (d < worst) {
            int j = K_;
            for (; j > 0; j--) {
                if (dist[j - 1] > d) { dist[j] = dist[j - 1]; nbr[j] = nbr[j - 1]; }
                else break;
            }
            dist[j] = d; nbr[j] = m;
            worst = dist[K_];
        }
    }

    int* o = g_idx + ((size_t)b * N_ + n) * K_;
#pragma unroll
    for (int k = 0; k < K_; k++) o[k] = nbr[k + 1];
}

// ---------------------------------------------------------------------------
// f32x2 helpers
// ---------------------------------------------------------------------------
__device__ __forceinline__ ull pack2(float lo, float hi)
{
    ull r;
    asm("mov.b64 %0, {%1, %2};" : "=l"(r) : "f"(lo), "f"(hi));
    return r;
}
__device__ __forceinline__ void unpack2(ull v, float& lo, float& hi)
{
    asm("mov.b64 {%0, %1}, %2;" : "=f"(lo), "=f"(hi) : "l"(v));
}
__device__ __forceinline__ ull ffma2(ull a, ull b, ull c)
{
    ull d;
    asm("fma.rn.f32x2 %0, %1, %2, %3;" : "=l"(d) : "l"(a), "l"(b), "l"(c));
    return d;
}
__device__ __forceinline__ float gelu_exact(float x)
{
    return 0.5f * x * (1.0f + erff(x * 0.70710678118654752440f));
}

// ---------------------------------------------------------------------------
// Kernel 2: fused edge MLP + mean over K, register-tiled GEMMs.
// Block handles NPB=4 points -> A[64x128] @ W1[128x256] -> gelu -> @ W2 -> gelu
// -> mean over the 16 k-rows of each point.
// Thread tile: 8 M-rows (4 f32x2 pairs) x 8 N-cols (phase1) / 4 N-cols (phase2).
// ---------------------------------------------------------------------------
__global__ __launch_bounds__(256, 2) void mlp_kernel(
    const float* __restrict__ features,
    const float* __restrict__ W1, const float* __restrict__ b1,
    const float* __restrict__ W2, const float* __restrict__ b2,
    float* __restrict__ out)
{
    extern __shared__ float smem[];
    float* As   = smem;                      // [128][AST]  (A^T: [k][m])
    float* Hsm  = As  + 128 * AST;           // [256][HST]  (H^T: [j][m])
    float* red  = Hsm + 256 * HST;           // [8][128]
    float* cenS = red + 8 * P_;              // [4][64]
    int*   nbS  = (int*)(cenS + NPB * F_);   // [64]

    int blk = blockIdx.x;
    int b  = blk >> 8;
    int n0 = (blk & 255) * NPB;
    const float* Fb = features + (size_t)b * N_ * F_;
    int t = threadIdx.x;

    // centers + neighbor indices
    {
        int nl = t >> 6, f = t & 63;
        cenS[t] = Fb[(size_t)(n0 + nl) * F_ + f];
    }
    if (t < M_) nbS[t] = g_idx[((size_t)b * N_ + n0 + (t >> 4)) * K_ + (t & 15)];
    __syncthreads();

    // gather: As[f][m] = nbr-ctr, As[64+f][m] = ctr    (m = nl*16 + k)
#pragma unroll
    for (int i = 0; i < 16; i++) {
        int e  = t + i * 256;
        int nl = e >> 10;
        int k  = (e >> 6) & 15;
        int f  = e & 63;
        int m  = nl * K_ + k;
        float c = cenS[nl * F_ + f];
        float v = Fb[(size_t)nbS[m] * F_ + f];
        As[f * AST + m]        = v - c;
        As[(F_ + f) * AST + m] = c;
    }
    __syncthreads();

    int tm = t & 7;        // M group (8 rows each)
    int tn = t >> 3;       // 0..31

    // ---------------- phase 1: A[64x128] @ W1[128x256] ----------------
    {
        int nb1 = tn * 8;
        ull acc[4][8];
#pragma unroll
        for (int j = 0; j < 8; j++) {
            float bv = b1[nb1 + j];
            ull p = pack2(bv, bv);
#pragma unroll
            for (int mp = 0; mp < 4; mp++) acc[mp][j] = p;
        }
        const float* w1p = W1 + nb1;
        const float* ap  = As + tm * 8;
#pragma unroll 4
        for (int k = 0; k < 2 * F_; k++) {
            float4 wa = *(const float4*)(w1p + k * H_);
            float4 wb = *(const float4*)(w1p + k * H_ + 4);
            ull w[8];
            w[0] = pack2(wa.x, wa.x); w[1] = pack2(wa.y, wa.y);
            w[2] = pack2(wa.z, wa.z); w[3] = pack2(wa.w, wa.w);
            w[4] = pack2(wb.x, wb.x); w[5] = pack2(wb.y, wb.y);
            w[6] = pack2(wb.z, wb.z); w[7] = pack2(wb.w, wb.w);
            const ull* ar = (const ull*)(ap + k * AST);
            ull a0 = ar[0], a1 = ar[1], a2 = ar[2], a3 = ar[3];
#pragma unroll
            for (int j = 0; j < 8; j++) {
                acc[0][j] = ffma2(a0, w[j], acc[0][j]);
                acc[1][j] = ffma2(a1, w[j], acc[1][j]);
                acc[2][j] = ffma2(a2, w[j], acc[2][j]);
                acc[3][j] = ffma2(a3, w[j], acc[3][j]);
            }
        }
        // epilogue: gelu -> Hsm (transposed [j][m])
#pragma unroll
        for (int j = 0; j < 8; j++) {
#pragma unroll
            for (int mp = 0; mp < 4; mp++) {
                float lo, hi; unpack2(acc[mp][j], lo, hi);
                float2 g = make_float2(gelu_exact(lo), gelu_exact(hi));
                *(float2*)(Hsm + (nb1 + j) * HST + tm * 8 + 2 * mp) = g;
            }
        }
    }
    __syncthreads();

    // ---------------- phase 2: H[64x256] @ W2[256x128] ----------------
    {
        int n2 = tn * 4;
        ull acc[4][4];
#pragma unroll
        for (int j = 0; j < 4; j++) {
            float bv = b2[n2 + j];
            ull p = pack2(bv, bv);
#pragma unroll
            for (int mp = 0; mp < 4; mp++) acc[mp][j] = p;
        }
        const float* w2p = W2 + n2;
        const float* hp  = Hsm + tm * 8;
#pragma unroll 4
        for (int k = 0; k < H_; k++) {
            float4 wv = *(const float4*)(w2p + k * P_);
            ull w[4];
            w[0] = pack2(wv.x, wv.x); w[1] = pack2(wv.y, wv.y);
            w[2] = pack2(wv.z, wv.z); w[3] = pack2(wv.w, wv.w);
            const ull* hr = (const ull*)(hp + k * HST);
            ull a0 = hr[0], a1 = hr[1], a2 = hr[2], a3 = hr[3];
#pragma unroll
            for (int j = 0; j < 4; j++) {
                acc[0][j] = ffma2(a0, w[j], acc[0][j]);
                acc[1][j] = ffma2(a1, w[j], acc[1][j]);
                acc[2][j] = ffma2(a2, w[j], acc[2][j]);
                acc[3][j] = ffma2(a3, w[j], acc[3][j]);
            }
        }
        // epilogue: gelu + partial sum over this thread's 8 k-rows
        float s[4] = {0.f, 0.f, 0.f, 0.f};
#pragma unroll
        for (int mp = 0; mp < 4; mp++) {
#pragma unroll
            for (int j = 0; j < 4; j++) {
                float lo, hi; unpack2(acc[mp][j], lo, hi);
                s[j] += gelu_exact(lo) + gelu_exact(hi);
            }
        }
#pragma unroll
        for (int j = 0; j < 4; j++) red[tm * P_ + n2 + j] = s[j];
        __syncthreads();
        if (!(tm & 1)) {
            int nrow = n0 + (tm >> 1);
#pragma unroll
            for (int j = 0; j < 4; j++) {
                float v = red[tm * P_ + n2 + j] + red[(tm + 1) * P_ + n2 + j];
                out[((size_t)b * N_ + nrow) * P_ + n2 + j] = v * (1.0f / 16.0f);
            }
        }
    }
}

// ---------------------------------------------------------------------------
extern "C" void kernel_launch(void* const* d_in, const int* in_sizes, int n_in,
                              void* d_out, int out_size)
{
    const float* points   = (const float*)d_in[0];
    const float* features = (const float*)d_in[1];
    const float* W1       = (const float*)d_in[2];
    const float* b1       = (const float*)d_in[3];
    const float* W2       = (const float*)d_in[4];
    const float* b2       = (const float*)d_in[5];
    float* out = (float*)d_out;

    const int smem_bytes = (128 * AST + 256 * HST + 8 * P_ + NPB * F_) * 4 + 64 * 4;
    cudaFuncSetAttribute(mlp_kernel, cudaFuncAttributeMaxDynamicSharedMemorySize,
                         smem_bytes);

    knn_kernel<<<B_ * 4, 256>>>(points);
    mlp_kernel<<<(B_ * N_) / NPB, 256, smem_bytes>>>(features, W1, b1, W2, b2, out);
}

// round 6
// speedup vs baseline: 1.2682x; 1.1361x over previous
#include <cuda_runtime.h>
#include <math_constants.h>

#define B_   32
#define N_   1024
#define F_   64
#define K_   16
#define P_   128
#define H_   256     // 2*P
#define NPB  4       // points per block
#define M_   (NPB * K_)   // 64 GEMM rows per block
#define AST  68      // padded SMEM row stride (floats), 16B-aligned
#define HST  68

typedef unsigned long long ull;

__device__ int g_idx[B_ * N_ * K_];

// ---------------------------------------------------------------------------
// Kernel 1: pairwise distances + top-(K+1) selection (drop self).
// ---------------------------------------------------------------------------
__global__ __launch_bounds__(256) void knn_kernel(const float* __restrict__ points)
{
    __shared__ float4 pts[N_];
    int b = blockIdx.x >> 2;
    int rowbase = (blockIdx.x & 3) << 8;
    const float* P = points + (size_t)b * N_ * 3;
    for (int i = threadIdx.x; i < N_; i += 256) {
        float x = P[i * 3 + 0], y = P[i * 3 + 1], z = P[i * 3 + 2];
        pts[i] = make_float4(x, y, z, x * x + y * y + z * z);
    }
    __syncthreads();

    int n = rowbase + threadIdx.x;
    float4 pn = pts[n];

    float dist[K_ + 1];
    int   nbr[K_ + 1];
#pragma unroll
    for (int j = 0; j <= K_; j++) { dist[j] = CUDART_INF_F; nbr[j] = 0; }
    float worst = CUDART_INF_F;

    for (int m = 0; m < N_; m++) {
        float4 pm = pts[m];
        float dot = pn.x * pm.x + pn.y * pm.y + pn.z * pm.z;
        float d = pn.w - 2.0f * dot + pm.w + 1e-5f;
        if (d < worst) {
            int j = K_;
            for (; j > 0; j--) {
                if (dist[j - 1] > d) { dist[j] = dist[j - 1]; nbr[j] = nbr[j - 1]; }
                else break;
            }
            dist[j] = d; nbr[j] = m;
            worst = dist[K_];
        }
    }

    int* o = g_idx + ((size_t)b * N_ + n) * K_;
#pragma unroll
    for (int k = 0; k < K_; k++) o[k] = nbr[k + 1];
}

// ---------------------------------------------------------------------------
// f32x2 helpers
// ---------------------------------------------------------------------------
__device__ __forceinline__ ull pack2(float lo, float hi)
{
    ull r;
    asm("mov.b64 %0, {%1, %2};" : "=l"(r) : "f"(lo), "f"(hi));
    return r;
}
__device__ __forceinline__ void unpack2(ull v, float& lo, float& hi)
{
    asm("mov.b64 {%0, %1}, %2;" : "=f"(lo), "=f"(hi) : "l"(v));
}
__device__ __forceinline__ ull ffma2(ull a, ull b, ull c)
{
    ull d;
    asm("fma.rn.f32x2 %0, %1, %2, %3;" : "=l"(d) : "l"(a), "l"(b), "l"(c));
    return d;
}
__device__ __forceinline__ float gelu_exact(float x)
{
    return 0.5f * x * (1.0f + erff(x * 0.70710678118654752440f));
}

// ---------------------------------------------------------------------------
// Kernel 2: fused edge MLP + mean over K.
// Block = NPB=4 points = 64 edge rows.
//   A[64x128] @ W1[128x256] -> gelu -> H[64x256] @ W2[256x128] -> gelu -> mean16
// Thread tiles: phase1 M'=4 x N'=16, phase2 M'=4 x N'=8 (tm = t&15, tn = t>>4).
// A operand: ONE dense LDS.128 per k (16 tm-chunks cover the 64-float row).
// ---------------------------------------------------------------------------
__global__ __launch_bounds__(256, 2) void mlp_kernel(
    const float* __restrict__ features,
    const float* __restrict__ W1, const float* __restrict__ b1,
    const float* __restrict__ W2, const float* __restrict__ b2,
    float* __restrict__ out)
{
    extern __shared__ float smem[];
    float* As   = smem;                      // [128][AST]  rows = feature idx, cols = m
    float* Hsm  = As  + 128 * AST;           // [256][HST]  rows = hidden idx,  cols = m
    float* cenS = Hsm + 256 * HST;           // [4][64]
    int*   nbS  = (int*)(cenS + NPB * F_);   // [64]

    int blk = blockIdx.x;
    int b  = blk >> 8;
    int n0 = (blk & 255) * NPB;
    const float* Fb = features + (size_t)b * N_ * F_;
    int t = threadIdx.x;

    {
        int nl = t >> 6, f = t & 63;
        cenS[t] = Fb[(size_t)(n0 + nl) * F_ + f];
    }
    if (t < M_) nbS[t] = g_idx[((size_t)b * N_ + n0 + (t >> 4)) * K_ + (t & 15)];
    __syncthreads();

    // gather: As[f][m] = nbr - ctr, As[64+f][m] = ctr   (m = nl*16 + k)
#pragma unroll
    for (int i = 0; i < 16; i++) {
        int e  = t + i * 256;
        int nl = e >> 10;
        int k  = (e >> 6) & 15;
        int f  = e & 63;
        int m  = nl * K_ + k;
        float c = cenS[nl * F_ + f];
        float v = Fb[(size_t)nbS[m] * F_ + f];
        As[f * AST + m]        = v - c;
        As[(F_ + f) * AST + m] = c;
    }
    __syncthreads();

    int tm = t & 15;       // m-chunk: rows tm*4 .. tm*4+3
    int tn = t >> 4;       // 0..15

    // ---------------- phase 1: A[64x128] @ W1[128x256] ----------------
    {
        int nb1 = tn * 16;
        ull acc[2][16];
#pragma unroll
        for (int j = 0; j < 16; j++) {
            float bv = __ldg(b1 + nb1 + j);
            ull p = pack2(bv, bv);
            acc[0][j] = p; acc[1][j] = p;
        }
        const float* w1p = W1 + nb1;
        const float* ap  = As + tm * 4;
#pragma unroll 2
        for (int k = 0; k < 2 * F_; k++) {
            float4 wa = *(const float4*)(w1p + k * H_ + 0);
            float4 wb = *(const float4*)(w1p + k * H_ + 4);
            float4 wc = *(const float4*)(w1p + k * H_ + 8);
            float4 wd = *(const float4*)(w1p + k * H_ + 12);
            float4 av = *(const float4*)(ap + k * AST);
            ull a0 = pack2(av.x, av.y);
            ull a1 = pack2(av.z, av.w);
            float ws[16] = {wa.x, wa.y, wa.z, wa.w, wb.x, wb.y, wb.z, wb.w,
                            wc.x, wc.y, wc.z, wc.w, wd.x, wd.y, wd.z, wd.w};
#pragma unroll
            for (int j = 0; j < 16; j++) {
                ull w = pack2(ws[j], ws[j]);
                acc[0][j] = ffma2(a0, w, acc[0][j]);
                acc[1][j] = ffma2(a1, w, acc[1][j]);
            }
        }
        // epilogue: gelu -> Hsm[j][m]
#pragma unroll
        for (int j = 0; j < 16; j++) {
            float g0, g1, g2, g3;
            unpack2(acc[0][j], g0, g1);
            unpack2(acc[1][j], g2, g3);
            float4 g = make_float4(gelu_exact(g0), gelu_exact(g1),
                                   gelu_exact(g2), gelu_exact(g3));
            *(float4*)(Hsm + (nb1 + j) * HST + tm * 4) = g;
        }
    }
    __syncthreads();

    // ---------------- phase 2: H[64x256] @ W2[256x128] ----------------
    {
        int n2 = tn * 8;
        ull acc[2][8];
#pragma unroll
        for (int j = 0; j < 8; j++) {
            float bv = __ldg(b2 + n2 + j);
            ull p = pack2(bv, bv);
            acc[0][j] = p; acc[1][j] = p;
        }
        const float* w2p = W2 + n2;
        const float* hp  = Hsm + tm * 4;
#pragma unroll 2
        for (int k = 0; k < H_; k++) {
            float4 wa = *(const float4*)(w2p + k * P_ + 0);
            float4 wb = *(const float4*)(w2p + k * P_ + 4);
            float4 hv = *(const float4*)(hp + k * HST);
            ull h0 = pack2(hv.x, hv.y);
            ull h1 = pack2(hv.z, hv.w);
            float ws[8] = {wa.x, wa.y, wa.z, wa.w, wb.x, wb.y, wb.z, wb.w};
#pragma unroll
            for (int j = 0; j < 8; j++) {
                ull w = pack2(ws[j], ws[j]);
                acc[0][j] = ffma2(h0, w, acc[0][j]);
                acc[1][j] = ffma2(h1, w, acc[1][j]);
            }
        }
        // epilogue: gelu + sum this thread's 4 k-rows, then reduce the 4-lane
        // group (tm..tm+3 are consecutive lanes) via shuffles -> mean over 16.
        float s[8];
#pragma unroll
        for (int j = 0; j < 8; j++) {
            float g0, g1, g2, g3;
            unpack2(acc[0][j], g0, g1);
            unpack2(acc[1][j], g2, g3);
            s[j] = gelu_exact(g0) + gelu_exact(g1) + gelu_exact(g2) + gelu_exact(g3);
        }
#pragma unroll
        for (int j = 0; j < 8; j++) {
            s[j] += __shfl_down_sync(0xffffffffu, s[j], 1);
            s[j] += __shfl_down_sync(0xffffffffu, s[j], 2);
        }
        if ((tm & 3) == 0) {
            int nrow = n0 + (tm >> 2);
            float4 o0 = make_float4(s[0], s[1], s[2], s[3]);
            float4 o1 = make_float4(s[4], s[5], s[6], s[7]);
            o0.x *= (1.0f / 16.0f); o0.y *= (1.0f / 16.0f);
            o0.z *= (1.0f / 16.0f); o0.w *= (1.0f / 16.0f);
            o1.x *= (1.0f / 16.0f); o1.y *= (1.0f / 16.0f);
            o1.z *= (1.0f / 16.0f); o1.w *= (1.0f / 16.0f);
            float* op = out + ((size_t)b * N_ + nrow) * P_ + n2;
            *(float4*)(op)     = o0;
            *(float4*)(op + 4) = o1;
        }
    }
}

// ---------------------------------------------------------------------------
extern "C" void kernel_launch(void* const* d_in, const int* in_sizes, int n_in,
                              void* d_out, int out_size)
{
    const float* points   = (const float*)d_in[0];
    const float* features = (const float*)d_in[1];
    const float* W1       = (const float*)d_in[2];
    const float* b1       = (const float*)d_in[3];
    const float* W2       = (const float*)d_in[4];
    const float* b2       = (const float*)d_in[5];
    float* out = (float*)d_out;

    const int smem_bytes = (128 * AST + 256 * HST + NPB * F_) * 4 + 64 * 4;
    cudaFuncSetAttribute(mlp_kernel, cudaFuncAttributeMaxDynamicSharedMemorySize,
                         smem_bytes);

    knn_kernel<<<B_ * 4, 256>>>(points);
    mlp_kernel<<<(B_ * N_) / NPB, 256, smem_bytes>>>(features, W1, b1, W2, b2, out);
}